// round 3
// baseline (speedup 1.0000x reference)
#include <cuda_runtime.h>
#include <stdint.h>

#define N_NODES 100000
#define N_EDGES 3200000
#define IN_CH 256
#define OUT_CH 256

// Scratch (static __device__ globals are the allowed scratch mechanism)
__device__ float g_aggx[(size_t)N_NODES * IN_CH];  // A @ x  (102.4 MB)
__device__ float g_deg[N_NODES];                   // in-degree per dst

// ---------------------------------------------------------------------------
// Zero the aggregation buffers
// ---------------------------------------------------------------------------
__global__ void zero_kernel() {
    const size_t stride = (size_t)gridDim.x * blockDim.x;
    size_t i = (size_t)blockIdx.x * blockDim.x + threadIdx.x;
    const size_t tot4 = (size_t)N_NODES * IN_CH / 4;
    float4 z = make_float4(0.f, 0.f, 0.f, 0.f);
    for (size_t j = i; j < tot4; j += stride)
        reinterpret_cast<float4*>(g_aggx)[j] = z;
    for (size_t j = i; j < N_NODES; j += stride)
        g_deg[j] = 0.f;
}

// ---------------------------------------------------------------------------
// Edge scatter: one warp per edge. agg[dst] += x[src]; deg[dst] += 1
// 256 floats/row = 64 float4; 32 lanes -> 2 float4 per lane.
// Vector red (red.global.add.v4.f32, sm_90+) quarters the atomic op count.
// Indices are int32 (JAX x64-disabled downcasts the int64 in the reference).
// ---------------------------------------------------------------------------
__global__ void scatter_kernel(const float* __restrict__ x,
                               const int* __restrict__ src,
                               const int* __restrict__ dst) {
    int warp = (int)((blockIdx.x * (size_t)blockDim.x + threadIdx.x) >> 5);
    int lane = threadIdx.x & 31;
    if (warp >= N_EDGES) return;

    int s = src[warp];
    int d = dst[warp];
    // Defensive: a bad index becomes a skipped edge (rel_err evidence),
    // not an illegal access (no evidence).
    if ((unsigned)s >= N_NODES || (unsigned)d >= N_NODES) return;

    const float4* xs = reinterpret_cast<const float4*>(x + (size_t)s * IN_CH);
    float* ad = g_aggx + (size_t)d * IN_CH;

#pragma unroll
    for (int i = 0; i < 2; i++) {
        float4 v = xs[lane + 32 * i];
        float* p = ad + (size_t)(lane + 32 * i) * 4;
        asm volatile("red.global.add.v4.f32 [%0], {%1, %2, %3, %4};"
                     :: "l"(p), "f"(v.x), "f"(v.y), "f"(v.z), "f"(v.w)
                     : "memory");
    }
    if (lane == 0)
        atomicAdd(&g_deg[d], 1.0f);
}

// ---------------------------------------------------------------------------
// GEMM + fused epilogue:
//   out[m][n] = ( aggx[m][:] . W[:][n] + deg[m]*bias[n] ) / max(deg[m], 1)
// Classic register-blocked SGEMM: BM=BN=64, BK=16, 256 threads, 4x4 microtile.
// ---------------------------------------------------------------------------
#define BM 64
#define BN 64
#define BK 16

__global__ __launch_bounds__(256) void gemm_epilogue_kernel(
    const float* __restrict__ W,
    const float* __restrict__ bias,
    float* __restrict__ out) {

    __shared__ float As[BK][BM + 4];   // +4 pad keeps float4 alignment, avoids conflicts
    __shared__ float Bs[BK][BN];

    const int bm = blockIdx.x * BM;
    const int bn = blockIdx.y * BN;
    const int tid = threadIdx.x;
    const int tx = tid & 15;           // 0..15 -> 4 output cols each
    const int ty = tid >> 4;           // 0..15 -> 4 output rows each

    // A-tile load mapping: 64 rows x 16 k, one float4 (along K) per thread
    const int arow = tid >> 2;         // 0..63
    const int akq  = (tid & 3) * 4;    // 0,4,8,12
    // B-tile load mapping: 16 rows x 64 n, one float4 (along N) per thread
    const int brow = tid >> 4;         // 0..15
    const int bnq  = (tid & 15) * 4;

    float acc[4][4] = {};

    for (int k0 = 0; k0 < IN_CH; k0 += BK) {
        // Load A tile (aggx) — transpose into As[k][m]
        float4 av = make_float4(0.f, 0.f, 0.f, 0.f);
        int m = bm + arow;
        if (m < N_NODES)
            av = *reinterpret_cast<const float4*>(
                g_aggx + (size_t)m * IN_CH + k0 + akq);
        As[akq + 0][arow] = av.x;
        As[akq + 1][arow] = av.y;
        As[akq + 2][arow] = av.z;
        As[akq + 3][arow] = av.w;

        // Load B tile (W) — direct
        *reinterpret_cast<float4*>(&Bs[brow][bnq]) =
            *reinterpret_cast<const float4*>(
                W + (size_t)(k0 + brow) * OUT_CH + bn + bnq);

        __syncthreads();

#pragma unroll
        for (int k = 0; k < BK; k++) {
            float4 a = *reinterpret_cast<const float4*>(&As[k][ty * 4]);
            float4 b = *reinterpret_cast<const float4*>(&Bs[k][tx * 4]);
            acc[0][0] += a.x * b.x; acc[0][1] += a.x * b.y;
            acc[0][2] += a.x * b.z; acc[0][3] += a.x * b.w;
            acc[1][0] += a.y * b.x; acc[1][1] += a.y * b.y;
            acc[1][2] += a.y * b.z; acc[1][3] += a.y * b.w;
            acc[2][0] += a.z * b.x; acc[2][1] += a.z * b.y;
            acc[2][2] += a.z * b.z; acc[2][3] += a.z * b.w;
            acc[3][0] += a.w * b.x; acc[3][1] += a.w * b.y;
            acc[3][2] += a.w * b.z; acc[3][3] += a.w * b.w;
        }
        __syncthreads();
    }

    // Fused epilogue: + deg*bias, then / max(deg,1)
    float4 bv = *reinterpret_cast<const float4*>(bias + bn + tx * 4);
#pragma unroll
    for (int i = 0; i < 4; i++) {
        int m = bm + ty * 4 + i;
        if (m >= N_NODES) continue;
        float d = g_deg[m];
        float inv = 1.0f / fmaxf(d, 1.0f);
        float4 o;
        o.x = (acc[i][0] + d * bv.x) * inv;
        o.y = (acc[i][1] + d * bv.y) * inv;
        o.z = (acc[i][2] + d * bv.z) * inv;
        o.w = (acc[i][3] + d * bv.w) * inv;
        *reinterpret_cast<float4*>(out + (size_t)m * OUT_CH + bn + tx * 4) = o;
    }
}

// ---------------------------------------------------------------------------
extern "C" void kernel_launch(void* const* d_in, const int* in_sizes, int n_in,
                              void* d_out, int out_size) {
    const float* x    = (const float*)d_in[0];
    const int*   src  = (const int*)d_in[1];
    const int*   dst  = (const int*)d_in[2];
    const float* W    = (const float*)d_in[3];
    const float* bias = (const float*)d_in[4];
    float* out = (float*)d_out;

    // 1) zero scratch
    zero_kernel<<<2048, 256>>>();

    // 2) scatter: one warp per edge -> 3.2M warps, 8 warps per block
    int blocks = (int)(((size_t)N_EDGES * 32 + 255) / 256);
    scatter_kernel<<<blocks, 256>>>(x, src, dst);

    // 3) GEMM with fused degree-normalization epilogue
    dim3 grid((N_NODES + BM - 1) / BM, OUT_CH / BN);
    gemm_epilogue_kernel<<<grid, 256>>>(W, bias, out);
}

// round 4
// speedup vs baseline: 2.0404x; 2.0404x over previous
#include <cuda_runtime.h>
#include <stdint.h>

#define N_NODES 100000
#define N_EDGES 3200000
#define IN_CH 256
#define OUT_CH 256

#define SCAN_BLK 1024
#define N_SCAN_BLKS ((N_NODES + SCAN_BLK - 1) / SCAN_BLK)   // 98

// ---------------------------------------------------------------------------
// Scratch (__device__ globals = allowed scratch)
// ---------------------------------------------------------------------------
__device__ int   g_cnt[N_NODES];            // in-degree (int)
__device__ int   g_cur[N_NODES];            // fill cursors
__device__ int   g_rowptr[N_NODES + 1];     // CSR row pointers (by dst)
__device__ int   g_tmp[N_NODES];            // per-block inclusive scan
__device__ int   g_bsum[256];               // block sums
__device__ int   g_esrc[N_EDGES];           // src ids bucketed by dst
__device__ float g_aggx[(size_t)N_NODES * IN_CH];  // A @ x

// ---------------------------------------------------------------------------
// 1) zero counters
// ---------------------------------------------------------------------------
__global__ void zero_cnt_kernel() {
    int i = blockIdx.x * blockDim.x + threadIdx.x;
    if (i < N_NODES) { g_cnt[i] = 0; g_cur[i] = 0; }
}

// ---------------------------------------------------------------------------
// 2) histogram of dst
// ---------------------------------------------------------------------------
__global__ void hist_kernel(const int* __restrict__ dst) {
    int e = blockIdx.x * blockDim.x + threadIdx.x;
    if (e < N_EDGES) {
        int d = dst[e];
        if ((unsigned)d < N_NODES) atomicAdd(&g_cnt[d], 1);
    }
}

// ---------------------------------------------------------------------------
// 3) scan: per-block inclusive (Hillis-Steele) + block sums
// ---------------------------------------------------------------------------
__global__ void scanA_kernel() {
    __shared__ int s[SCAN_BLK];
    int i = blockIdx.x * SCAN_BLK + threadIdx.x;
    int v = (i < N_NODES) ? g_cnt[i] : 0;
    s[threadIdx.x] = v;
    __syncthreads();
#pragma unroll
    for (int off = 1; off < SCAN_BLK; off <<= 1) {
        int t = (threadIdx.x >= off) ? s[threadIdx.x - off] : 0;
        __syncthreads();
        s[threadIdx.x] += t;
        __syncthreads();
    }
    if (i < N_NODES) g_tmp[i] = s[threadIdx.x];
    if (threadIdx.x == SCAN_BLK - 1) g_bsum[blockIdx.x] = s[SCAN_BLK - 1];
}

// 4) scan block sums (single block), convert to exclusive offsets
__global__ void scanB_kernel() {
    __shared__ int s[128];
    int v = (threadIdx.x < N_SCAN_BLKS) ? g_bsum[threadIdx.x] : 0;
    s[threadIdx.x] = v;
    __syncthreads();
#pragma unroll
    for (int off = 1; off < 128; off <<= 1) {
        int t = (threadIdx.x >= off) ? s[threadIdx.x - off] : 0;
        __syncthreads();
        s[threadIdx.x] += t;
        __syncthreads();
    }
    if (threadIdx.x < N_SCAN_BLKS) g_bsum[threadIdx.x] = s[threadIdx.x] - v;
}

// 5) add offsets -> row_ptr (row_ptr[i+1] = inclusive scan of counts)
__global__ void scanC_kernel() {
    int i = blockIdx.x * SCAN_BLK + threadIdx.x;
    if (i < N_NODES) g_rowptr[i + 1] = g_tmp[i] + g_bsum[blockIdx.x];
    if (i == 0) g_rowptr[0] = 0;
}

// ---------------------------------------------------------------------------
// 6) fill CSR buckets: esrc[rowptr[dst] + cursor++] = src
// ---------------------------------------------------------------------------
__global__ void fill_kernel(const int* __restrict__ src,
                            const int* __restrict__ dst) {
    int e = blockIdx.x * blockDim.x + threadIdx.x;
    if (e < N_EDGES) {
        int d = dst[e];
        int s = src[e];
        if ((unsigned)d >= N_NODES || (unsigned)s >= N_NODES) return;
        int pos = g_rowptr[d] + atomicAdd(&g_cur[d], 1);
        g_esrc[pos] = s;
    }
}

// ---------------------------------------------------------------------------
// 7) gather: agg[n] = sum over neighbors of x[src]. No atomics, one write/row.
// 64 threads per node (each owns one float4 channel slice), 4 nodes per block.
// ---------------------------------------------------------------------------
__global__ __launch_bounds__(256) void gather_kernel(const float* __restrict__ x) {
    int node = blockIdx.x * 4 + (threadIdx.x >> 6);
    int t = threadIdx.x & 63;
    if (node >= N_NODES) return;

    int beg = __ldg(&g_rowptr[node]);
    int end = __ldg(&g_rowptr[node + 1]);

    float4 acc = make_float4(0.f, 0.f, 0.f, 0.f);
    int e = beg;
    // 4-way unroll for MLP
    for (; e + 4 <= end; e += 4) {
        int s0 = __ldg(&g_esrc[e + 0]);
        int s1 = __ldg(&g_esrc[e + 1]);
        int s2 = __ldg(&g_esrc[e + 2]);
        int s3 = __ldg(&g_esrc[e + 3]);
        float4 v0 = __ldg((const float4*)(x + (size_t)s0 * IN_CH) + t);
        float4 v1 = __ldg((const float4*)(x + (size_t)s1 * IN_CH) + t);
        float4 v2 = __ldg((const float4*)(x + (size_t)s2 * IN_CH) + t);
        float4 v3 = __ldg((const float4*)(x + (size_t)s3 * IN_CH) + t);
        acc.x += v0.x + v1.x + v2.x + v3.x;
        acc.y += v0.y + v1.y + v2.y + v3.y;
        acc.z += v0.z + v1.z + v2.z + v3.z;
        acc.w += v0.w + v1.w + v2.w + v3.w;
    }
    for (; e < end; e++) {
        int s = __ldg(&g_esrc[e]);
        float4 v = __ldg((const float4*)(x + (size_t)s * IN_CH) + t);
        acc.x += v.x; acc.y += v.y; acc.z += v.z; acc.w += v.w;
    }
    *reinterpret_cast<float4*>(g_aggx + (size_t)node * IN_CH + t * 4) = acc;
}

// ---------------------------------------------------------------------------
// 8) GEMM + fused epilogue: out[m] = (agg[m] @ W + deg[m]*bias) / max(deg,1)
// BM=BN=128, BK=8, 256 threads, 8x8 microtile as 2x2 blocks of 4x4.
// ---------------------------------------------------------------------------
#define BM 128
#define BN 128
#define BK 8

__global__ __launch_bounds__(256) void gemm_epilogue_kernel(
    const float* __restrict__ W,
    const float* __restrict__ bias,
    float* __restrict__ out) {

    __shared__ float As[BK][BM + 4];
    __shared__ float Bs[BK][BN];

    const int bm = blockIdx.x * BM;
    const int bn = blockIdx.y * BN;
    const int tid = threadIdx.x;
    const int tx = tid & 15;
    const int ty = tid >> 4;

    // A load: 128 rows x 8 k = 256 float4, one per thread
    const int arow = tid >> 1;          // 0..127
    const int akq  = (tid & 1) * 4;     // 0 or 4
    // B load: 8 rows x 128 n = 256 float4, one per thread
    const int brow = tid >> 5;          // 0..7
    const int bnq  = (tid & 31) * 4;

    float acc[2][2][4][4] = {};

    for (int k0 = 0; k0 < IN_CH; k0 += BK) {
        int m = bm + arow;
        float4 av = make_float4(0.f, 0.f, 0.f, 0.f);
        if (m < N_NODES)
            av = *reinterpret_cast<const float4*>(
                g_aggx + (size_t)m * IN_CH + k0 + akq);
        As[akq + 0][arow] = av.x;
        As[akq + 1][arow] = av.y;
        As[akq + 2][arow] = av.z;
        As[akq + 3][arow] = av.w;

        *reinterpret_cast<float4*>(&Bs[brow][bnq]) =
            *reinterpret_cast<const float4*>(
                W + (size_t)(k0 + brow) * OUT_CH + bn + bnq);

        __syncthreads();

#pragma unroll
        for (int k = 0; k < BK; k++) {
            float4 a0 = *reinterpret_cast<const float4*>(&As[k][ty * 4]);
            float4 a1 = *reinterpret_cast<const float4*>(&As[k][64 + ty * 4]);
            float4 b0 = *reinterpret_cast<const float4*>(&Bs[k][tx * 4]);
            float4 b1 = *reinterpret_cast<const float4*>(&Bs[k][64 + tx * 4]);
            float av2[2][4] = {{a0.x, a0.y, a0.z, a0.w},
                               {a1.x, a1.y, a1.z, a1.w}};
            float bv2[2][4] = {{b0.x, b0.y, b0.z, b0.w},
                               {b1.x, b1.y, b1.z, b1.w}};
#pragma unroll
            for (int ia = 0; ia < 2; ia++)
#pragma unroll
                for (int i = 0; i < 4; i++)
#pragma unroll
                    for (int ib = 0; ib < 2; ib++)
#pragma unroll
                        for (int j = 0; j < 4; j++)
                            acc[ia][ib][i][j] += av2[ia][i] * bv2[ib][j];
        }
        __syncthreads();
    }

    // Epilogue: + deg*bias then / max(deg,1)
    float4 bias4[2];
    bias4[0] = *reinterpret_cast<const float4*>(bias + bn + tx * 4);
    bias4[1] = *reinterpret_cast<const float4*>(bias + bn + 64 + tx * 4);

#pragma unroll
    for (int ia = 0; ia < 2; ia++) {
#pragma unroll
        for (int i = 0; i < 4; i++) {
            int m = bm + ia * 64 + ty * 4 + i;
            if (m >= N_NODES) continue;
            float d = (float)g_cnt[m];
            float inv = 1.0f / fmaxf(d, 1.0f);
#pragma unroll
            for (int ib = 0; ib < 2; ib++) {
                float4 bb = bias4[ib];
                float4 o;
                o.x = (acc[ia][ib][i][0] + d * bb.x) * inv;
                o.y = (acc[ia][ib][i][1] + d * bb.y) * inv;
                o.z = (acc[ia][ib][i][2] + d * bb.z) * inv;
                o.w = (acc[ia][ib][i][3] + d * bb.w) * inv;
                *reinterpret_cast<float4*>(
                    out + (size_t)m * OUT_CH + bn + ib * 64 + tx * 4) = o;
            }
        }
    }
}

// ---------------------------------------------------------------------------
extern "C" void kernel_launch(void* const* d_in, const int* in_sizes, int n_in,
                              void* d_out, int out_size) {
    const float* x    = (const float*)d_in[0];
    const int*   src  = (const int*)d_in[1];
    const int*   dst  = (const int*)d_in[2];
    const float* W    = (const float*)d_in[3];
    const float* bias = (const float*)d_in[4];
    float* out = (float*)d_out;

    int eb = (N_EDGES + 255) / 256;

    zero_cnt_kernel<<<(N_NODES + 255) / 256, 256>>>();
    hist_kernel<<<eb, 256>>>(dst);
    scanA_kernel<<<N_SCAN_BLKS, SCAN_BLK>>>();
    scanB_kernel<<<1, 128>>>();
    scanC_kernel<<<N_SCAN_BLKS, SCAN_BLK>>>();
    fill_kernel<<<eb, 256>>>(src, dst);
    gather_kernel<<<(N_NODES + 3) / 4, 256>>>(x);

    dim3 grid((N_NODES + BM - 1) / BM, OUT_CH / BN);
    gemm_epilogue_kernel<<<grid, 256>>>(W, bias, out);
}

// round 6
// speedup vs baseline: 3.3332x; 1.6337x over previous
#include <cuda_runtime.h>
#include <cuda_fp16.h>
#include <stdint.h>

#define N_NODES 100000
#define N_EDGES 3200000
#define IN_CH 256
#define OUT_CH 256

#define TILE_M 128
#define N_TILES ((N_NODES + TILE_M - 1) / TILE_M)      // 782
#define A_ROWS (N_TILES * TILE_M)                      // 100096 (padded)

#define SCAN_BLK 1024
#define N_SCAN_BLKS ((N_NODES + SCAN_BLK - 1) / SCAN_BLK)   // 98

// ---------------------------------------------------------------------------
// Scratch
// ---------------------------------------------------------------------------
__device__ int g_cnt[N_NODES];
__device__ int g_cur[N_NODES];
__device__ int g_rowptr[N_NODES + 1];
__device__ int g_tmp[N_NODES];
__device__ int g_bsum[256];
__device__ int g_esrc[N_EDGES];
__device__ __align__(16) __half g_Ah[(size_t)A_ROWS * IN_CH];   // agg, fp16 row-major
__device__ __align__(16) __half g_Wh[IN_CH * OUT_CH];           // W, fp16 row-major [k][n]

// ---------------------------------------------------------------------------
// CSR build
// ---------------------------------------------------------------------------
__global__ void zero_cnt_kernel() {
    int i = blockIdx.x * blockDim.x + threadIdx.x;
    if (i < N_NODES) { g_cnt[i] = 0; g_cur[i] = 0; }
}

__global__ void hist_kernel(const int* __restrict__ dst) {
    int e = blockIdx.x * blockDim.x + threadIdx.x;
    if (e < N_EDGES) {
        int d = dst[e];
        if ((unsigned)d < N_NODES) atomicAdd(&g_cnt[d], 1);
    }
}

__global__ void scanA_kernel() {
    __shared__ int s[SCAN_BLK];
    int i = blockIdx.x * SCAN_BLK + threadIdx.x;
    int v = (i < N_NODES) ? g_cnt[i] : 0;
    s[threadIdx.x] = v;
    __syncthreads();
#pragma unroll
    for (int off = 1; off < SCAN_BLK; off <<= 1) {
        int t = (threadIdx.x >= off) ? s[threadIdx.x - off] : 0;
        __syncthreads();
        s[threadIdx.x] += t;
        __syncthreads();
    }
    if (i < N_NODES) g_tmp[i] = s[threadIdx.x];
    if (threadIdx.x == SCAN_BLK - 1) g_bsum[blockIdx.x] = s[SCAN_BLK - 1];
}

__global__ void scanB_kernel() {
    __shared__ int s[128];
    int v = (threadIdx.x < N_SCAN_BLKS) ? g_bsum[threadIdx.x] : 0;
    s[threadIdx.x] = v;
    __syncthreads();
#pragma unroll
    for (int off = 1; off < 128; off <<= 1) {
        int t = (threadIdx.x >= off) ? s[threadIdx.x - off] : 0;
        __syncthreads();
        s[threadIdx.x] += t;
        __syncthreads();
    }
    if (threadIdx.x < N_SCAN_BLKS) g_bsum[threadIdx.x] = s[threadIdx.x] - v;
}

__global__ void scanC_kernel() {
    int i = blockIdx.x * SCAN_BLK + threadIdx.x;
    if (i < N_NODES) g_rowptr[i + 1] = g_tmp[i] + g_bsum[blockIdx.x];
    if (i == 0) g_rowptr[0] = 0;
}

__global__ void fill_kernel(const int* __restrict__ src,
                            const int* __restrict__ dst) {
    int e = blockIdx.x * blockDim.x + threadIdx.x;
    if (e < N_EDGES) {
        int d = dst[e];
        int s = src[e];
        if ((unsigned)d >= N_NODES || (unsigned)s >= N_NODES) return;
        int pos = g_rowptr[d] + atomicAdd(&g_cur[d], 1);
        g_esrc[pos] = s;
    }
}

// ---------------------------------------------------------------------------
// W -> fp16 row-major
// ---------------------------------------------------------------------------
__global__ void prep_w_kernel(const float* __restrict__ W) {
    int idx = blockIdx.x * blockDim.x + threadIdx.x;
    if (idx < IN_CH * OUT_CH) g_Wh[idx] = __float2half(W[idx]);
}

// ---------------------------------------------------------------------------
// Gather: agg[n] = sum_neighbors x[src], fp32 accumulate, fp16 row-major out.
// 64 threads/node, thread t owns channels 4t..4t+3 (one 8-byte store).
// ---------------------------------------------------------------------------
__global__ __launch_bounds__(256) void gather_kernel(const float* __restrict__ x) {
    int node = blockIdx.x * 4 + (threadIdx.x >> 6);
    int t = threadIdx.x & 63;
    if (node >= N_NODES) return;

    int beg = __ldg(&g_rowptr[node]);
    int end = __ldg(&g_rowptr[node + 1]);

    float4 acc = make_float4(0.f, 0.f, 0.f, 0.f);
    int e = beg;
    for (; e + 4 <= end; e += 4) {
        int s0 = __ldg(&g_esrc[e + 0]);
        int s1 = __ldg(&g_esrc[e + 1]);
        int s2 = __ldg(&g_esrc[e + 2]);
        int s3 = __ldg(&g_esrc[e + 3]);
        float4 v0 = __ldg((const float4*)(x + (size_t)s0 * IN_CH) + t);
        float4 v1 = __ldg((const float4*)(x + (size_t)s1 * IN_CH) + t);
        float4 v2 = __ldg((const float4*)(x + (size_t)s2 * IN_CH) + t);
        float4 v3 = __ldg((const float4*)(x + (size_t)s3 * IN_CH) + t);
        acc.x += v0.x + v1.x + v2.x + v3.x;
        acc.y += v0.y + v1.y + v2.y + v3.y;
        acc.z += v0.z + v1.z + v2.z + v3.z;
        acc.w += v0.w + v1.w + v2.w + v3.w;
    }
    for (; e < end; e++) {
        int s = __ldg(&g_esrc[e]);
        float4 v = __ldg((const float4*)(x + (size_t)s * IN_CH) + t);
        acc.x += v.x; acc.y += v.y; acc.z += v.z; acc.w += v.w;
    }

    __half2 h01 = __floats2half2_rn(acc.x, acc.y);
    __half2 h23 = __floats2half2_rn(acc.z, acc.w);
    __half2* p = reinterpret_cast<__half2*>(g_Ah + (size_t)node * IN_CH + 4 * t);
    p[0] = h01;
    p[1] = h23;
}

// ---------------------------------------------------------------------------
// Tensor-core GEMM (mma.sync m16n8k16 fp16->fp32) + fused epilogue.
// One CTA per 128-row tile; 8 warps x 16 M-rows; N processed in 4 chunks of 64.
// smem: A 128x(256+8) halves, B chunk 256x(64+8) halves; +8 pad => ldmatrix
// conflict-free (row stride 33 / 9 sixteen-byte groups, both ≡1 mod 8).
// ---------------------------------------------------------------------------
#define A_PAD 8
#define A_LDA (IN_CH + A_PAD)                 // 264 halves
#define B_PAD 8
#define B_LDB (64 + B_PAD)                    // 72 halves
#define SMEM_A_HALVES (TILE_M * A_LDA)        // 33792
#define SMEM_B_HALVES (IN_CH * B_LDB)         // 18432
#define SMEM_GEMM_BYTES ((SMEM_A_HALVES + SMEM_B_HALVES) * 2)  // 104448

static __device__ __forceinline__ uint32_t smem_u32(const void* p) {
    uint32_t a;
    asm("{ .reg .u64 t; cvta.to.shared.u64 t, %1; cvt.u32.u64 %0, t; }" : "=r"(a) : "l"(p));
    return a;
}

__global__ __launch_bounds__(256) void gemm_tc_kernel(
    const float* __restrict__ bias,
    float* __restrict__ out) {

    extern __shared__ __half smem[];
    __half* sA = smem;
    __half* sB = smem + SMEM_A_HALVES;

    const int tid = threadIdx.x;
    const int wid = tid >> 5;
    const int lane = tid & 31;
    const int tile_base = blockIdx.x * TILE_M;

    // ---- Load A tile (zero pad rows beyond N_NODES) ----
    {
        const uint4* srcA = reinterpret_cast<const uint4*>(g_Ah + (size_t)tile_base * IN_CH);
        for (int i = tid; i < TILE_M * 32; i += 256) {       // 32 uint4 per row
            int row = i >> 5;
            int c8 = i & 31;
            uint4 v = make_uint4(0, 0, 0, 0);
            if (tile_base + row < N_NODES) v = srcA[row * 32 + c8];
            *reinterpret_cast<uint4*>(sA + row * A_LDA + c8 * 8) = v;
        }
    }

    // ---- Per-thread fragment addresses ----
    // A: a_row = wid*16 + (l&7) + ((l>>3)&1)*8 ; a_col = k0 + (l>>4)*8
    const int fr = (lane & 7) + ((lane >> 3) & 1) * 8;
    const int fc8 = (lane >> 4) * 8;
    uint32_t aAddrBase = smem_u32(sA + (wid * 16 + fr) * A_LDA + fc8);
    // B: b_row = k0 + fr ; b_col = n0 + fc8
    uint32_t bAddrBase = smem_u32(sB + fr * B_LDB + fc8);

    // ---- Epilogue row constants ----
    const int r1 = wid * 16 + (lane >> 2);
    const int r2 = r1 + 8;
    const int m1 = tile_base + r1;
    const int m2 = tile_base + r2;
    float d1 = 0.f, inv1 = 1.f, d2 = 0.f, inv2 = 1.f;
    if (m1 < N_NODES) { d1 = (float)__ldg(&g_cnt[m1]); inv1 = 1.f / fmaxf(d1, 1.f); }
    if (m2 < N_NODES) { d2 = (float)__ldg(&g_cnt[m2]); inv2 = 1.f / fmaxf(d2, 1.f); }
    const int ccol = 2 * (lane & 3);

    __syncthreads();

    for (int nb = 0; nb < 4; nb++) {
        // ---- Load B chunk [256 k][64 n] ----
        {
            const uint4* srcB = reinterpret_cast<const uint4*>(g_Wh);
            for (int i = tid; i < IN_CH * 8; i += 256) {     // 8 uint4 per row
                int row = i >> 3;
                int c8 = i & 7;
                uint4 v = srcB[row * 32 + nb * 8 + c8];
                *reinterpret_cast<uint4*>(sB + row * B_LDB + c8 * 8) = v;
            }
        }
        __syncthreads();

        float acc[8][4];
#pragma unroll
        for (int t = 0; t < 8; t++)
#pragma unroll
            for (int j = 0; j < 4; j++) acc[t][j] = 0.f;

#pragma unroll
        for (int k0 = 0; k0 < IN_CH; k0 += 16) {
            uint32_t a0, a1, a2, a3;
            asm volatile(
                "ldmatrix.sync.aligned.m8n8.x4.shared.b16 {%0,%1,%2,%3}, [%4];"
                : "=r"(a0), "=r"(a1), "=r"(a2), "=r"(a3)
                : "r"(aAddrBase + k0 * 2));
#pragma unroll
            for (int p = 0; p < 4; p++) {
                uint32_t b0, b1, b2, b3;
                asm volatile(
                    "ldmatrix.sync.aligned.m8n8.x4.trans.shared.b16 {%0,%1,%2,%3}, [%4];"
                    : "=r"(b0), "=r"(b1), "=r"(b2), "=r"(b3)
                    : "r"(bAddrBase + (k0 * B_LDB + p * 16) * 2));
                asm volatile(
                    "mma.sync.aligned.m16n8k16.row.col.f32.f16.f16.f32 "
                    "{%0,%1,%2,%3}, {%4,%5,%6,%7}, {%8,%9}, {%0,%1,%2,%3};"
                    : "+f"(acc[2 * p][0]), "+f"(acc[2 * p][1]),
                      "+f"(acc[2 * p][2]), "+f"(acc[2 * p][3])
                    : "r"(a0), "r"(a1), "r"(a2), "r"(a3), "r"(b0), "r"(b1));
                asm volatile(
                    "mma.sync.aligned.m16n8k16.row.col.f32.f16.f16.f32 "
                    "{%0,%1,%2,%3}, {%4,%5,%6,%7}, {%8,%9}, {%0,%1,%2,%3};"
                    : "+f"(acc[2 * p + 1][0]), "+f"(acc[2 * p + 1][1]),
                      "+f"(acc[2 * p + 1][2]), "+f"(acc[2 * p + 1][3])
                    : "r"(a0), "r"(a1), "r"(a2), "r"(a3), "r"(b2), "r"(b3));
            }
        }

        // ---- Epilogue: (v + deg*bias[n]) / max(deg,1), direct stores ----
#pragma unroll
        for (int t = 0; t < 8; t++) {
            int n = nb * 64 + t * 8 + ccol;
            float b0 = __ldg(&bias[n]);
            float b1 = __ldg(&bias[n + 1]);
            if (m1 < N_NODES) {
                float2 o;
                o.x = (acc[t][0] + d1 * b0) * inv1;
                o.y = (acc[t][1] + d1 * b1) * inv1;
                *reinterpret_cast<float2*>(out + (size_t)m1 * OUT_CH + n) = o;
            }
            if (m2 < N_NODES) {
                float2 o;
                o.x = (acc[t][2] + d2 * b0) * inv2;
                o.y = (acc[t][3] + d2 * b1) * inv2;
                *reinterpret_cast<float2*>(out + (size_t)m2 * OUT_CH + n) = o;
            }
        }
        __syncthreads();
    }
}

// ---------------------------------------------------------------------------
extern "C" void kernel_launch(void* const* d_in, const int* in_sizes, int n_in,
                              void* d_out, int out_size) {
    const float* x    = (const float*)d_in[0];
    const int*   src  = (const int*)d_in[1];
    const int*   dst  = (const int*)d_in[2];
    const float* W    = (const float*)d_in[3];
    const float* bias = (const float*)d_in[4];
    float* out = (float*)d_out;

    int eb = (N_EDGES + 255) / 256;

    zero_cnt_kernel<<<(N_NODES + 255) / 256, 256>>>();
    hist_kernel<<<eb, 256>>>(dst);
    scanA_kernel<<<N_SCAN_BLKS, SCAN_BLK>>>();
    scanB_kernel<<<1, 128>>>();
    scanC_kernel<<<N_SCAN_BLKS, SCAN_BLK>>>();
    fill_kernel<<<eb, 256>>>(src, dst);

    prep_w_kernel<<<(IN_CH * OUT_CH + 255) / 256, 256>>>(W);
    gather_kernel<<<(N_NODES + 3) / 4, 256>>>(x);

    cudaFuncSetAttribute(gemm_tc_kernel,
                         cudaFuncAttributeMaxDynamicSharedMemorySize, SMEM_GEMM_BYTES);
    gemm_tc_kernel<<<N_TILES, 256, SMEM_GEMM_BYTES>>>(bias, out);
}

// round 7
// speedup vs baseline: 4.1471x; 1.2442x over previous
#include <cuda_runtime.h>
#include <cuda_fp16.h>
#include <stdint.h>

#define N_NODES 100000
#define N_EDGES 3200000
#define IN_CH 256
#define OUT_CH 256

#define TILE_M 128
#define N_TILES ((N_NODES + TILE_M - 1) / TILE_M)      // 782

#define SCAN_BLK 1024
#define N_SCAN_BLKS ((N_NODES + SCAN_BLK - 1) / SCAN_BLK)   // 98

// ---------------------------------------------------------------------------
// Scratch
// ---------------------------------------------------------------------------
__device__ int g_cnt[N_NODES];
__device__ int g_cur[N_NODES];
__device__ int g_rowptr[N_NODES + 1];
__device__ int g_tmp[N_NODES];
__device__ int g_bsum[256];
__device__ int g_esrc[N_EDGES];
__device__ __align__(16) __half g_xh[(size_t)N_NODES * IN_CH];  // x in fp16 (51 MB)
__device__ __align__(16) __half g_Ah[(size_t)N_NODES * IN_CH];  // agg, fp16 row-major
__device__ __align__(16) __half g_Wh[IN_CH * OUT_CH];           // W, fp16 [k][n]

// ---------------------------------------------------------------------------
// CSR build
// ---------------------------------------------------------------------------
__global__ void zero_cnt_kernel() {
    int i = blockIdx.x * blockDim.x + threadIdx.x;
    if (i < N_NODES) { g_cnt[i] = 0; g_cur[i] = 0; }
}

__global__ void hist_kernel(const int* __restrict__ dst) {
    int e = blockIdx.x * blockDim.x + threadIdx.x;
    if (e < N_EDGES) {
        int d = dst[e];
        if ((unsigned)d < N_NODES) atomicAdd(&g_cnt[d], 1);
    }
}

__global__ void scanA_kernel() {
    __shared__ int s[SCAN_BLK];
    int i = blockIdx.x * SCAN_BLK + threadIdx.x;
    int v = (i < N_NODES) ? g_cnt[i] : 0;
    s[threadIdx.x] = v;
    __syncthreads();
#pragma unroll
    for (int off = 1; off < SCAN_BLK; off <<= 1) {
        int t = (threadIdx.x >= off) ? s[threadIdx.x - off] : 0;
        __syncthreads();
        s[threadIdx.x] += t;
        __syncthreads();
    }
    if (i < N_NODES) g_tmp[i] = s[threadIdx.x];
    if (threadIdx.x == SCAN_BLK - 1) g_bsum[blockIdx.x] = s[SCAN_BLK - 1];
}

__global__ void scanB_kernel() {
    __shared__ int s[128];
    int v = (threadIdx.x < N_SCAN_BLKS) ? g_bsum[threadIdx.x] : 0;
    s[threadIdx.x] = v;
    __syncthreads();
#pragma unroll
    for (int off = 1; off < 128; off <<= 1) {
        int t = (threadIdx.x >= off) ? s[threadIdx.x - off] : 0;
        __syncthreads();
        s[threadIdx.x] += t;
        __syncthreads();
    }
    if (threadIdx.x < N_SCAN_BLKS) g_bsum[threadIdx.x] = s[threadIdx.x] - v;
}

__global__ void scanC_kernel() {
    int i = blockIdx.x * SCAN_BLK + threadIdx.x;
    if (i < N_NODES) g_rowptr[i + 1] = g_tmp[i] + g_bsum[blockIdx.x];
    if (i == 0) g_rowptr[0] = 0;
}

__global__ void fill_kernel(const int* __restrict__ src,
                            const int* __restrict__ dst) {
    int e = blockIdx.x * blockDim.x + threadIdx.x;
    if (e < N_EDGES) {
        int d = dst[e];
        int s = src[e];
        if ((unsigned)d >= N_NODES || (unsigned)s >= N_NODES) return;
        int pos = g_rowptr[d] + atomicAdd(&g_cur[d], 1);
        g_esrc[pos] = s;
    }
}

// ---------------------------------------------------------------------------
// fp16 conversions: W and x
// ---------------------------------------------------------------------------
__global__ void prep_w_kernel(const float* __restrict__ W) {
    int idx = blockIdx.x * blockDim.x + threadIdx.x;
    if (idx < IN_CH * OUT_CH) g_Wh[idx] = __float2half(W[idx]);
}

__global__ void prep_x_kernel(const float* __restrict__ x) {
    const size_t tot4 = (size_t)N_NODES * IN_CH / 4;
    const size_t stride = (size_t)gridDim.x * blockDim.x;
    for (size_t i = (size_t)blockIdx.x * blockDim.x + threadIdx.x; i < tot4; i += stride) {
        float4 v = reinterpret_cast<const float4*>(x)[i];
        __half2 h01 = __floats2half2_rn(v.x, v.y);
        __half2 h23 = __floats2half2_rn(v.z, v.w);
        reinterpret_cast<__half2*>(g_xh)[2 * i + 0] = h01;
        reinterpret_cast<__half2*>(g_xh)[2 * i + 1] = h23;
    }
}

// ---------------------------------------------------------------------------
// Gather in fp16: agg[n] = sum_neighbors xh[src], fp32 accumulate.
// 32 threads/node, lane owns 8 halves (one uint4 = 16B load per edge).
// 8 nodes per 256-thread block.
// ---------------------------------------------------------------------------
__global__ __launch_bounds__(256) void gather_kernel() {
    int node = blockIdx.x * 8 + (threadIdx.x >> 5);
    int lane = threadIdx.x & 31;
    if (node >= N_NODES) return;

    int beg = __ldg(&g_rowptr[node]);
    int end = __ldg(&g_rowptr[node + 1]);

    float2 a0 = {0.f, 0.f}, a1 = {0.f, 0.f}, a2 = {0.f, 0.f}, a3 = {0.f, 0.f};

    const uint4* xh = reinterpret_cast<const uint4*>(g_xh);  // 32 uint4 per row

#define ACC_U4(v)                                                          \
    do {                                                                   \
        float2 f;                                                          \
        f = __half22float2(*reinterpret_cast<const __half2*>(&(v).x));     \
        a0.x += f.x; a0.y += f.y;                                          \
        f = __half22float2(*reinterpret_cast<const __half2*>(&(v).y));     \
        a1.x += f.x; a1.y += f.y;                                          \
        f = __half22float2(*reinterpret_cast<const __half2*>(&(v).z));     \
        a2.x += f.x; a2.y += f.y;                                          \
        f = __half22float2(*reinterpret_cast<const __half2*>(&(v).w));     \
        a3.x += f.x; a3.y += f.y;                                          \
    } while (0)

    int e = beg;
    for (; e + 4 <= end; e += 4) {
        int s0 = __ldg(&g_esrc[e + 0]);
        int s1 = __ldg(&g_esrc[e + 1]);
        int s2 = __ldg(&g_esrc[e + 2]);
        int s3 = __ldg(&g_esrc[e + 3]);
        uint4 v0 = __ldg(&xh[(size_t)s0 * 32 + lane]);
        uint4 v1 = __ldg(&xh[(size_t)s1 * 32 + lane]);
        uint4 v2 = __ldg(&xh[(size_t)s2 * 32 + lane]);
        uint4 v3 = __ldg(&xh[(size_t)s3 * 32 + lane]);
        ACC_U4(v0); ACC_U4(v1); ACC_U4(v2); ACC_U4(v3);
    }
    for (; e < end; e++) {
        int s = __ldg(&g_esrc[e]);
        uint4 v = __ldg(&xh[(size_t)s * 32 + lane]);
        ACC_U4(v);
    }
#undef ACC_U4

    // pack 8 accumulated floats -> 4 half2 -> one 16B store
    uint4 o;
    __half2 h;
    h = __floats2half2_rn(a0.x, a0.y); o.x = *reinterpret_cast<uint32_t*>(&h);
    h = __floats2half2_rn(a1.x, a1.y); o.y = *reinterpret_cast<uint32_t*>(&h);
    h = __floats2half2_rn(a2.x, a2.y); o.z = *reinterpret_cast<uint32_t*>(&h);
    h = __floats2half2_rn(a3.x, a3.y); o.w = *reinterpret_cast<uint32_t*>(&h);
    reinterpret_cast<uint4*>(g_Ah)[(size_t)node * 32 + lane] = o;
}

// ---------------------------------------------------------------------------
// Tensor-core GEMM (mma.sync m16n8k16 fp16->fp32) + fused epilogue.
// One CTA per 128-row tile; 8 warps x 16 M-rows; N in 4 chunks of 64.
// ---------------------------------------------------------------------------
#define A_PAD 8
#define A_LDA (IN_CH + A_PAD)                 // 264 halves
#define B_PAD 8
#define B_LDB (64 + B_PAD)                    // 72 halves
#define SMEM_A_HALVES (TILE_M * A_LDA)        // 33792
#define SMEM_B_HALVES (IN_CH * B_LDB)         // 18432
#define SMEM_GEMM_BYTES ((SMEM_A_HALVES + SMEM_B_HALVES) * 2)  // 104448

static __device__ __forceinline__ uint32_t smem_u32(const void* p) {
    uint32_t a;
    asm("{ .reg .u64 t; cvta.to.shared.u64 t, %1; cvt.u32.u64 %0, t; }" : "=r"(a) : "l"(p));
    return a;
}

__global__ __launch_bounds__(256) void gemm_tc_kernel(
    const float* __restrict__ bias,
    float* __restrict__ out) {

    extern __shared__ __half smem[];
    __half* sA = smem;
    __half* sB = smem + SMEM_A_HALVES;

    const int tid = threadIdx.x;
    const int wid = tid >> 5;
    const int lane = tid & 31;
    const int tile_base = blockIdx.x * TILE_M;

    // ---- Load A tile (zero pad rows beyond N_NODES) ----
    {
        const uint4* srcA = reinterpret_cast<const uint4*>(g_Ah + (size_t)tile_base * IN_CH);
        for (int i = tid; i < TILE_M * 32; i += 256) {
            int row = i >> 5;
            int c8 = i & 31;
            uint4 v = make_uint4(0, 0, 0, 0);
            if (tile_base + row < N_NODES) v = srcA[row * 32 + c8];
            *reinterpret_cast<uint4*>(sA + row * A_LDA + c8 * 8) = v;
        }
    }

    // ---- Per-thread fragment addresses ----
    const int fr = (lane & 7) + ((lane >> 3) & 1) * 8;
    const int fc8 = (lane >> 4) * 8;
    uint32_t aAddrBase = smem_u32(sA + (wid * 16 + fr) * A_LDA + fc8);
    uint32_t bAddrBase = smem_u32(sB + fr * B_LDB + fc8);

    // ---- Epilogue row constants ----
    const int r1 = wid * 16 + (lane >> 2);
    const int r2 = r1 + 8;
    const int m1 = tile_base + r1;
    const int m2 = tile_base + r2;
    float d1 = 0.f, inv1 = 1.f, d2 = 0.f, inv2 = 1.f;
    if (m1 < N_NODES) { d1 = (float)__ldg(&g_cnt[m1]); inv1 = 1.f / fmaxf(d1, 1.f); }
    if (m2 < N_NODES) { d2 = (float)__ldg(&g_cnt[m2]); inv2 = 1.f / fmaxf(d2, 1.f); }
    const int ccol = 2 * (lane & 3);

    __syncthreads();

    for (int nb = 0; nb < 4; nb++) {
        // ---- Load B chunk [256 k][64 n] ----
        {
            const uint4* srcB = reinterpret_cast<const uint4*>(g_Wh);
            for (int i = tid; i < IN_CH * 8; i += 256) {
                int row = i >> 3;
                int c8 = i & 7;
                uint4 v = srcB[row * 32 + nb * 8 + c8];
                *reinterpret_cast<uint4*>(sB + row * B_LDB + c8 * 8) = v;
            }
        }
        __syncthreads();

        float acc[8][4];
#pragma unroll
        for (int t = 0; t < 8; t++)
#pragma unroll
            for (int j = 0; j < 4; j++) acc[t][j] = 0.f;

#pragma unroll
        for (int k0 = 0; k0 < IN_CH; k0 += 16) {
            uint32_t a0, a1, a2, a3;
            asm volatile(
                "ldmatrix.sync.aligned.m8n8.x4.shared.b16 {%0,%1,%2,%3}, [%4];"
                : "=r"(a0), "=r"(a1), "=r"(a2), "=r"(a3)
                : "r"(aAddrBase + k0 * 2));
#pragma unroll
            for (int p = 0; p < 4; p++) {
                uint32_t b0, b1, b2, b3;
                asm volatile(
                    "ldmatrix.sync.aligned.m8n8.x4.trans.shared.b16 {%0,%1,%2,%3}, [%4];"
                    : "=r"(b0), "=r"(b1), "=r"(b2), "=r"(b3)
                    : "r"(bAddrBase + (k0 * B_LDB + p * 16) * 2));
                asm volatile(
                    "mma.sync.aligned.m16n8k16.row.col.f32.f16.f16.f32 "
                    "{%0,%1,%2,%3}, {%4,%5,%6,%7}, {%8,%9}, {%0,%1,%2,%3};"
                    : "+f"(acc[2 * p][0]), "+f"(acc[2 * p][1]),
                      "+f"(acc[2 * p][2]), "+f"(acc[2 * p][3])
                    : "r"(a0), "r"(a1), "r"(a2), "r"(a3), "r"(b0), "r"(b1));
                asm volatile(
                    "mma.sync.aligned.m16n8k16.row.col.f32.f16.f16.f32 "
                    "{%0,%1,%2,%3}, {%4,%5,%6,%7}, {%8,%9}, {%0,%1,%2,%3};"
                    : "+f"(acc[2 * p + 1][0]), "+f"(acc[2 * p + 1][1]),
                      "+f"(acc[2 * p + 1][2]), "+f"(acc[2 * p + 1][3])
                    : "r"(a0), "r"(a1), "r"(a2), "r"(a3), "r"(b2), "r"(b3));
            }
        }

        // ---- Epilogue: (v + deg*bias[n]) / max(deg,1), direct stores ----
#pragma unroll
        for (int t = 0; t < 8; t++) {
            int n = nb * 64 + t * 8 + ccol;
            float b0 = __ldg(&bias[n]);
            float b1 = __ldg(&bias[n + 1]);
            if (m1 < N_NODES) {
                float2 o;
                o.x = (acc[t][0] + d1 * b0) * inv1;
                o.y = (acc[t][1] + d1 * b1) * inv1;
                *reinterpret_cast<float2*>(out + (size_t)m1 * OUT_CH + n) = o;
            }
            if (m2 < N_NODES) {
                float2 o;
                o.x = (acc[t][2] + d2 * b0) * inv2;
                o.y = (acc[t][3] + d2 * b1) * inv2;
                *reinterpret_cast<float2*>(out + (size_t)m2 * OUT_CH + n) = o;
            }
        }
        __syncthreads();
    }
}

// ---------------------------------------------------------------------------
extern "C" void kernel_launch(void* const* d_in, const int* in_sizes, int n_in,
                              void* d_out, int out_size) {
    const float* x    = (const float*)d_in[0];
    const int*   src  = (const int*)d_in[1];
    const int*   dst  = (const int*)d_in[2];
    const float* W    = (const float*)d_in[3];
    const float* bias = (const float*)d_in[4];
    float* out = (float*)d_out;

    int eb = (N_EDGES + 255) / 256;

    zero_cnt_kernel<<<(N_NODES + 255) / 256, 256>>>();
    hist_kernel<<<eb, 256>>>(dst);
    scanA_kernel<<<N_SCAN_BLKS, SCAN_BLK>>>();
    scanB_kernel<<<1, 128>>>();
    scanC_kernel<<<N_SCAN_BLKS, SCAN_BLK>>>();
    fill_kernel<<<eb, 256>>>(src, dst);

    prep_w_kernel<<<(IN_CH * OUT_CH + 255) / 256, 256>>>(W);
    prep_x_kernel<<<2048, 256>>>(x);
    gather_kernel<<<(N_NODES + 7) / 8, 256>>>();

    cudaFuncSetAttribute(gemm_tc_kernel,
                         cudaFuncAttributeMaxDynamicSharedMemorySize, SMEM_GEMM_BYTES);
    gemm_tc_kernel<<<N_TILES, 256, SMEM_GEMM_BYTES>>>(bias, out);
}